// round 6
// baseline (speedup 1.0000x reference)
#include <cuda_runtime.h>
#include <math.h>

#define NH   200
#define BR   8
#define IND  120
#define OD   35
#define TT   250
#define PER  15
#define BPC  2      // batches per CTA
#define W2S  201    // padded W2 row stride (conflict-free smem)

typedef unsigned long long u64;

__device__ __forceinline__ u64 pk2(float lo, float hi) {
    u64 r; asm("mov.b64 %0,{%1,%2};" : "=l"(r) : "f"(lo), "f"(hi)); return r;
}
__device__ __forceinline__ void upk2(u64 v, float& lo, float& hi) {
    asm("mov.b64 {%0,%1},%2;" : "=f"(lo), "=f"(hi) : "l"(v));
}
__device__ __forceinline__ u64 fma2(u64 a, u64 b, u64 c) {
    u64 d; asm("fma.rn.f32x2 %0,%1,%2,%3;" : "=l"(d) : "l"(a), "l"(b), "l"(c)); return d;
}
__device__ __forceinline__ u64 mul2(u64 a, u64 b) {
    u64 d; asm("mul.rn.f32x2 %0,%1,%2;" : "=l"(d) : "l"(a), "l"(b)); return d;
}
__device__ __forceinline__ u64 add2(u64 a, u64 b) {
    u64 d; asm("add.rn.f32x2 %0,%1,%2;" : "=l"(d) : "l"(a), "l"(b)); return d;
}
__device__ __forceinline__ float sigm(float v) { return 1.0f / (1.0f + expf(-v)); }

__global__ __launch_bounds__(256, 2)
void snn_r6_kernel(const float* __restrict__ x,
                   const float* __restrict__ W1,
                   const float* __restrict__ b1,
                   const float* __restrict__ tau_m1,
                   const float* __restrict__ tau_n1,
                   const float* __restrict__ W2,
                   const float* __restrict__ b2,
                   const float* __restrict__ tau_m2,
                   float* __restrict__ out)
{
    __shared__ __align__(16) float xsbuf[2][BPC][128]; // double-buffered padded inputs
    __shared__ u64  spkB[NH];                          // packed spikes (2 batches)
    __shared__ u64  psum[7 * OD];                      // packed readout partials
    __shared__ float W2s[OD * W2S];                    // padded readout weights
    __shared__ float accS[BPC][OD];

    const int tid = threadIdx.x;
    const int b0  = blockIdx.x * BPC;

    // ---- W2 -> smem (padded rows) ----
    for (int i = tid; i < OD * NH; i += 256) {
        int o = i / NH, n = i - o * NH;
        W2s[o * W2S + n] = W2[i];
    }
    // zero slot-15 pads: 2 bufs x 2 batches x 8 branches = 32
    if (tid < 32) {
        int buf = tid >> 4, rest = tid & 15, bj = rest >> 3, k = rest & 7;
        xsbuf[buf][bj][k * 16 + 15] = 0.0f;
    }

    // ---- per-neuron weights, (1-beta) folded, slot-pair packed ----
    u64   w2r[64];                 // 8 branches x 8 slot-pairs
    float beta[BR], dst[BPC][BR];
    float a1 = 0.f, oma1 = 0.f, bb1 = 0.f, mem1[BPC], spkv[BPC];

    if (tid < NH) {
        #pragma unroll
        for (int k = 0; k < BR; k++) {
            float bt = sigm(tau_n1[tid * BR + k]);
            beta[k] = bt;
            float sc = 1.0f - bt;
            const float* src = W1 + (size_t)tid * (BR * IND) + k * IND + k * PER;
            float wr[16];
            #pragma unroll
            for (int j = 0; j < PER; j++) wr[j] = src[j] * sc;
            wr[15] = 0.0f;
            #pragma unroll
            for (int m = 0; m < 8; m++) w2r[k * 8 + m] = pk2(wr[2 * m], wr[2 * m + 1]);
        }
        a1 = sigm(tau_m1[tid]); oma1 = 1.0f - a1; bb1 = b1[tid];
    } else {
        #pragma unroll
        for (int k = 0; k < BR; k++) beta[k] = 0.0f;
        #pragma unroll
        for (int p = 0; p < 64; p++) w2r[p] = 0ULL;
    }
    #pragma unroll
    for (int bj = 0; bj < BPC; bj++) {
        mem1[bj] = 0.f; spkv[bj] = 0.f;
        #pragma unroll
        for (int k = 0; k < BR; k++) dst[bj][k] = 0.f;
    }

    // ---- readout integrator state (threads 0..34) ----
    float a2 = 0.f, bb2 = 0.f, mem2[BPC], racc[BPC];
    #pragma unroll
    for (int bj = 0; bj < BPC; bj++) { mem2[bj] = 0.f; racc[bj] = 0.f; }
    if (tid < OD) { a2 = sigm(tau_m2[tid]); bb2 = b2[tid]; }

    // ---- readout slice mapping: tid = ss*35 + oo, 7 slices x 29 neurons ----
    const int ss = tid / OD, oo = tid - ss * OD;
    const int rn0 = ss * 29;
    const int rn1 = (rn0 + 29 < NH) ? (rn0 + 29) : NH;
    const bool doRO = (tid < 7 * OD);

    // ---- x loader: tid<240 loads one (batch, feature)/step ----
    const float* xptr = nullptr;
    int lbj = 0, xoff = 0;
    if (tid < BPC * IND) {
        lbj = tid / IND;
        int f = tid - lbj * IND;
        int c = f / 40, dd = f - c * 40;
        xptr = x + ((size_t)((b0 + lbj) * 3 + c) * TT) * 40 + dd;
        xoff = (f / PER) * 16 + (f % PER);
    }

    if (tid < BPC * IND) xsbuf[0][lbj][xoff] = xptr[0];
    __syncthreads();

    for (int t = 0; t < TT; t++) {
        const int cur = t & 1;

        // prefetch next step's input
        float xn = 0.0f;
        if (tid < BPC * IND && (t + 1) < TT) xn = __ldg(xptr + (size_t)(t + 1) * 40);

        // ---- dendrite + soma (threads 0..199) ----
        if (tid < NH) {
            #pragma unroll
            for (int bj = 0; bj < BPC; bj++) {
                const ulonglong2* xv = (const ulonglong2*)xsbuf[cur][bj];
                float l = bb1;
                #pragma unroll
                for (int k = 0; k < BR; k++) {
                    ulonglong2 v0 = xv[k * 4 + 0];
                    ulonglong2 v1 = xv[k * 4 + 1];
                    ulonglong2 v2 = xv[k * 4 + 2];
                    ulonglong2 v3 = xv[k * 4 + 3];
                    u64 sA = mul2(v0.x, w2r[k * 8 + 0]);
                    u64 sB = mul2(v0.y, w2r[k * 8 + 1]);
                    sA = fma2(v1.x, w2r[k * 8 + 2], sA);
                    sB = fma2(v1.y, w2r[k * 8 + 3], sB);
                    sA = fma2(v2.x, w2r[k * 8 + 4], sA);
                    sB = fma2(v2.y, w2r[k * 8 + 5], sB);
                    sA = fma2(v3.x, w2r[k * 8 + 6], sA);
                    sB = fma2(v3.y, w2r[k * 8 + 7], sB);
                    u64 I2 = add2(sA, sB);
                    float il, ih; upk2(I2, il, ih);
                    // weights pre-scaled by (1-beta): d = beta*d + I'
                    float d = fmaf(beta[k], dst[bj][k], il + ih);
                    dst[bj][k] = d;
                    l += d;
                }
                float m = fmaf(a1, mem1[bj] - spkv[bj], oma1 * l);
                mem1[bj] = m;
                spkv[bj] = (m > 1.0f) ? 1.0f : 0.0f;
            }
            spkB[tid] = pk2(spkv[0], spkv[1]);
        }
        __syncthreads();   // (C): spikes visible; xsbuf[cur] reads done

        // stage next xt into the other buffer
        if (tid < BPC * IND && (t + 1) < TT) xsbuf[cur ^ 1][lbj][xoff] = xn;

        // ---- readout partials: 245 threads, 35 outputs x 7 slices ----
        if (doRO) {
            const float* wrow = &W2s[oo * W2S];
            u64 pA = 0ULL, pB = 0ULL;
            int nn = rn0;
            for (; nn + 2 <= rn1; nn += 2) {
                float w0 = wrow[nn], w1 = wrow[nn + 1];
                pA = fma2(spkB[nn],     pk2(w0, w0), pA);
                pB = fma2(spkB[nn + 1], pk2(w1, w1), pB);
            }
            if (nn < rn1) {
                float w0 = wrow[nn];
                pA = fma2(spkB[nn], pk2(w0, w0), pA);
            }
            psum[tid] = add2(pA, pB);
        }
        __syncthreads();   // (D): psum + next xs visible

        // ---- reduce + leaky readout integrator (threads 0..34) ----
        if (tid < OD) {
            u64 r = psum[tid];
            #pragma unroll
            for (int s2 = 1; s2 < 7; s2++) r = add2(r, psum[s2 * OD + tid]);
            float r0, r1; upk2(r, r0, r1);
            float t0 = r0 + bb2;
            float m0 = fmaf(a2, mem2[0] - t0, t0);
            mem2[0] = m0; racc[0] += m0;
            float t1 = r1 + bb2;
            float m1 = fmaf(a2, mem2[1] - t1, t1);
            mem2[1] = m1; racc[1] += m1;
        }
    }

    // ---- epilogue: log_softmax(acc/T) per batch ----
    if (tid < OD) {
        #pragma unroll
        for (int bj = 0; bj < BPC; bj++)
            accS[bj][tid] = racc[bj] * (1.0f / TT);
    }
    __syncthreads();
    if (tid < BPC * OD) {
        int bj = tid / OD, o = tid - bj * OD;
        float m = -INFINITY;
        #pragma unroll
        for (int i = 0; i < OD; i++) m = fmaxf(m, accS[bj][i]);
        float se = 0.0f;
        #pragma unroll
        for (int i = 0; i < OD; i++) se += expf(accS[bj][i] - m);
        out[(size_t)(b0 + bj) * OD + o] = accS[bj][o] - m - logf(se);
    }
}

extern "C" void kernel_launch(void* const* d_in, const int* in_sizes, int n_in,
                              void* d_out, int out_size)
{
    const float* x      = (const float*)d_in[0];
    const float* W1     = (const float*)d_in[1];
    const float* b1     = (const float*)d_in[2];
    const float* tau_m1 = (const float*)d_in[3];
    const float* tau_n1 = (const float*)d_in[4];
    const float* W2     = (const float*)d_in[5];
    const float* b2     = (const float*)d_in[6];
    const float* tau_m2 = (const float*)d_in[7];
    float* out = (float*)d_out;

    const int B = in_sizes[0] / (3 * TT * 40);   // 512
    snn_r6_kernel<<<B / BPC, 256>>>(x, W1, b1, tau_m1, tau_n1, W2, b2, tau_m2, out);
}

// round 7
// speedup vs baseline: 1.6969x; 1.6969x over previous
#include <cuda_runtime.h>
#include <math.h>

#define NH    200
#define BR    8
#define IND   120
#define OD    35
#define TT    250
#define PER   15
#define BPC   4
#define NTHR  576
#define ROBASE 416          // first readout thread
#define NSL   4             // readout slices
#define SLN   50            // neurons per slice
#define W2SU  201           // W2dup row stride in u64

typedef unsigned long long u64;

__device__ __forceinline__ u64 pk2(float lo, float hi) {
    u64 r; asm("mov.b64 %0,{%1,%2};" : "=l"(r) : "f"(lo), "f"(hi)); return r;
}
__device__ __forceinline__ void upk2(u64 v, float& lo, float& hi) {
    asm("mov.b64 {%0,%1},%2;" : "=f"(lo), "=f"(hi) : "l"(v));
}
__device__ __forceinline__ u64 fma2(u64 a, u64 b, u64 c) {
    u64 d; asm("fma.rn.f32x2 %0,%1,%2,%3;" : "=l"(d) : "l"(a), "l"(b), "l"(c)); return d;
}
__device__ __forceinline__ u64 mul2(u64 a, u64 b) {
    u64 d; asm("mul.rn.f32x2 %0,%1,%2;" : "=l"(d) : "l"(a), "l"(b)); return d;
}
__device__ __forceinline__ u64 add2(u64 a, u64 b) {
    u64 d; asm("add.rn.f32x2 %0,%1,%2;" : "=l"(d) : "l"(a), "l"(b)); return d;
}
__device__ __forceinline__ float sigm(float v) { return 1.0f / (1.0f + expf(-v)); }

// ---- dynamic smem layout (bytes, 16B aligned) ----
#define OFF_W1   0                        // u64 [64][200]  = 102400
#define OFF_W2   102400                   // u64 [35][201]  = 56280 (pad to 56288)
#define OFF_XS   (OFF_W2 + 56288)         // float [2][4][128] = 4096
#define OFF_SPK  (OFF_XS + 4096)          // u64 [2][400]   = 6400
#define OFF_PS   (OFF_SPK + 6400)         // u64 [2][140][2]= 4480
#define OFF_ACC  (OFF_PS + 4480)          // float [4][35]  = 560 (pad 576)
#define SMEM_TOTAL (OFF_ACC + 576)        // ~170.3 KB

__global__ __launch_bounds__(NTHR, 1)
void snn_r7_kernel(const float* __restrict__ x,
                   const float* __restrict__ W1,
                   const float* __restrict__ b1,
                   const float* __restrict__ tau_m1,
                   const float* __restrict__ tau_n1,
                   const float* __restrict__ W2,
                   const float* __restrict__ b2,
                   const float* __restrict__ tau_m2,
                   float* __restrict__ out)
{
    extern __shared__ __align__(16) char smem[];
    u64  *w1sm  = (u64*)(smem + OFF_W1);            // [slot=k*8+m][n] pair-packed, (1-beta)-folded
    u64  *w2d   = (u64*)(smem + OFF_W2);            // [o][n] duplicated lanes, stride 201
    float (*xs)[BPC][128] = (float (*)[BPC][128])(smem + OFF_XS);
    u64  *spkSm = (u64*)(smem + OFF_SPK);           // [buf][n*2+pair]
    u64  *ps    = (u64*)(smem + OFF_PS);            // [buf][r][pair]
    float (*accS)[OD] = (float (*)[OD])(smem + OFF_ACC);

    const int tid = threadIdx.x;
    const int b0  = blockIdx.x * BPC;

    // ---- roles ----
    const bool isDen = (tid < 2 * NH);              // 0..399: (neuron, batch-half)
    const int  n     = tid >> 1;
    const int  half  = tid & 1;                     // batches {2h, 2h+1}, spike pair = h
    const int  r     = tid - ROBASE;                // readout index
    const bool doRO  = (r >= 0 && r < NSL * OD);    // 416..555
    const int  ss    = doRO ? (r / OD) : 0;
    const int  oo    = doRO ? (r - ss * OD) : 0;
    const int  rn0   = ss * SLN;
    const bool doRED = (r >= 0 && r < OD);          // 416..450

    // ---- init W1 -> smem: fold (1-beta), pair-pack, slot-major ----
    for (int i = tid; i < NH * BR; i += NTHR) {
        int nn = i >> 3, k = i & 7;
        float bt = sigm(tau_n1[nn * BR + k]);
        float sc = 1.0f - bt;
        const float* src = W1 + (size_t)nn * (BR * IND) + k * IND + k * PER;
        float wr[16];
        #pragma unroll
        for (int j = 0; j < PER; j++) wr[j] = src[j] * sc;
        wr[15] = 0.0f;
        #pragma unroll
        for (int m = 0; m < 8; m++)
            w1sm[(k * 8 + m) * NH + nn] = pk2(wr[2 * m], wr[2 * m + 1]);
    }
    // ---- init W2 duplicated ----
    for (int i = tid; i < OD * NH; i += NTHR) {
        int o = i / NH, nn = i - o * NH;
        float wv = W2[i];
        w2d[o * W2SU + nn] = pk2(wv, wv);
    }
    // zero slot-15 pads of xs
    if (tid < 64) {
        int buf = tid >> 5, rest = tid & 31, bj = rest >> 3, k = rest & 7;
        xs[buf][bj][k * 16 + 15] = 0.0f;
    }

    // ---- dendrite/soma persistent state ----
    float beta[BR], dA[BR], dB[BR];
    float a1 = 0.f, oma1 = 0.f, bb1 = 0.f;
    float memA = 0.f, memB = 0.f, spA = 0.f, spB = 0.f;
    if (isDen) {
        #pragma unroll
        for (int k = 0; k < BR; k++) beta[k] = sigm(tau_n1[n * BR + k]);
        a1 = sigm(tau_m1[n]); oma1 = 1.0f - a1; bb1 = b1[n];
    }
    #pragma unroll
    for (int k = 0; k < BR; k++) { dA[k] = 0.f; dB[k] = 0.f; }

    // ---- integrator state (readout threads r<35) ----
    float a2 = 0.f, bb2 = 0.f, mem2[BPC], racc[BPC];
    #pragma unroll
    for (int bj = 0; bj < BPC; bj++) { mem2[bj] = 0.f; racc[bj] = 0.f; }
    if (doRED) { a2 = sigm(tau_m2[r]); bb2 = b2[r]; }

    // ---- x loader: 480 threads, one (batch, feature) each ----
    const bool isLd = (tid < 496) && !(tid >= 400 && tid < ROBASE);
    const float* xptr = nullptr;
    int lbj = 0, xoff = 0;
    if (isLd) {
        int lt = (tid < 400) ? tid : tid - 16;
        lbj = lt / IND;
        int f = lt - lbj * IND;
        int c = f / 40, dd = f - c * 40;
        xptr = x + ((size_t)((b0 + lbj) * 3 + c) * TT) * 40 + dd;
        xoff = (f / PER) * 16 + (f % PER);
    }
    if (isLd) xs[0][lbj][xoff] = xptr[0];
    __syncthreads();

    // ======== main loop: 3-stage pipeline, 1 barrier/iteration ========
    for (int t = 0; t < TT + 2; t++) {
        const int cur = t & 1, prv = cur ^ 1;

        float xn = 0.0f;
        if (isLd && t < TT - 1) xn = __ldg(xptr + (size_t)(t + 1) * 40);

        // ---- stage 1: dendrite + soma for step t (threads 0..399) ----
        if (t < TT && isDen) {
            const ulonglong2* xvA = (const ulonglong2*)xs[cur][2 * half];
            const ulonglong2* xvB = (const ulonglong2*)xs[cur][2 * half + 1];
            float l0 = bb1, l1 = bb1;
            #pragma unroll
            for (int k = 0; k < BR; k++) {
                const u64* wk = &w1sm[k * (8 * NH) + n];
                u64 w0 = wk[0],        w1v = wk[NH],      w2v = wk[2 * NH],  w3 = wk[3 * NH];
                u64 w4 = wk[4 * NH],   w5 = wk[5 * NH],   w6 = wk[6 * NH],   w7 = wk[7 * NH];

                ulonglong2 a0 = xvA[k * 4 + 0];
                ulonglong2 a1v = xvA[k * 4 + 1];
                ulonglong2 a2v = xvA[k * 4 + 2];
                ulonglong2 a3 = xvA[k * 4 + 3];
                u64 sA = mul2(a0.x, w0);
                u64 sB = mul2(a0.y, w1v);
                sA = fma2(a1v.x, w2v, sA);
                sB = fma2(a1v.y, w3, sB);
                sA = fma2(a2v.x, w4, sA);
                sB = fma2(a2v.y, w5, sB);
                sA = fma2(a3.x, w6, sA);
                sB = fma2(a3.y, w7, sB);
                u64 IA = add2(sA, sB);
                float il, ih; upk2(IA, il, ih);
                float da = fmaf(beta[k], dA[k], il + ih);
                dA[k] = da; l0 += da;

                ulonglong2 c0 = xvB[k * 4 + 0];
                ulonglong2 c1 = xvB[k * 4 + 1];
                ulonglong2 c2 = xvB[k * 4 + 2];
                ulonglong2 c3 = xvB[k * 4 + 3];
                u64 tA = mul2(c0.x, w0);
                u64 tB = mul2(c0.y, w1v);
                tA = fma2(c1.x, w2v, tA);
                tB = fma2(c1.y, w3, tB);
                tA = fma2(c2.x, w4, tA);
                tB = fma2(c2.y, w5, tB);
                tA = fma2(c3.x, w6, tA);
                tB = fma2(c3.y, w7, tB);
                u64 IB = add2(tA, tB);
                float jl, jh; upk2(IB, jl, jh);
                float db = fmaf(beta[k], dB[k], jl + jh);
                dB[k] = db; l1 += db;
            }
            float m0 = fmaf(a1, memA - spA, oma1 * l0);
            memA = m0; spA = (m0 > 1.0f) ? 1.0f : 0.0f;
            float m1 = fmaf(a1, memB - spB, oma1 * l1);
            memB = m1; spB = (m1 > 1.0f) ? 1.0f : 0.0f;
            spkSm[cur * 400 + n * 2 + half] = pk2(spA, spB);
        }

        // stage next x into the other buffer
        if (isLd && t < TT - 1) xs[prv][lbj][xoff] = xn;

        // ---- stage 2: readout partials for step t-1 (threads 416..555) ----
        if (doRO && t >= 1 && t <= TT) {
            const ulonglong2* sp2 = (const ulonglong2*)&spkSm[prv * 400];
            const u64* wrow = &w2d[oo * W2SU];
            u64 q0a = 0, q0b = 0, q1a = 0, q1b = 0;
            #pragma unroll 5
            for (int nn = rn0; nn < rn0 + SLN; nn += 2) {
                ulonglong2 sa = sp2[nn];
                u64 wa = wrow[nn];
                q0a = fma2(sa.x, wa, q0a);
                q1a = fma2(sa.y, wa, q1a);
                ulonglong2 sb = sp2[nn + 1];
                u64 wb = wrow[nn + 1];
                q0b = fma2(sb.x, wb, q0b);
                q1b = fma2(sb.y, wb, q1b);
            }
            ulonglong2 st;
            st.x = add2(q0a, q0b);
            st.y = add2(q1a, q1b);
            ((ulonglong2*)&ps[cur * 280])[r] = st;
        }

        // ---- stage 3: reduce + integrator for step t-2 (threads 416..450) ----
        if (doRED && t >= 2) {
            const ulonglong2* pv = (const ulonglong2*)&ps[prv * 280];
            ulonglong2 v0 = pv[r], v1 = pv[OD + r], v2 = pv[2 * OD + r], v3 = pv[3 * OD + r];
            u64 s0 = add2(add2(v0.x, v1.x), add2(v2.x, v3.x));
            u64 s1 = add2(add2(v0.y, v1.y), add2(v2.y, v3.y));
            float r0, r1, r2, r3;
            upk2(s0, r0, r1); upk2(s1, r2, r3);
            float t0 = r0 + bb2, t1 = r1 + bb2, t2 = r2 + bb2, t3 = r3 + bb2;
            float m0 = fmaf(a2, mem2[0] - t0, t0); mem2[0] = m0; racc[0] += m0;
            float m1 = fmaf(a2, mem2[1] - t1, t1); mem2[1] = m1; racc[1] += m1;
            float m2 = fmaf(a2, mem2[2] - t2, t2); mem2[2] = m2; racc[2] += m2;
            float m3 = fmaf(a2, mem2[3] - t3, t3); mem2[3] = m3; racc[3] += m3;
        }

        __syncthreads();
    }

    // ---- epilogue: log_softmax(acc/T) per batch ----
    if (doRED) {
        #pragma unroll
        for (int bj = 0; bj < BPC; bj++)
            accS[bj][r] = racc[bj] * (1.0f / TT);
    }
    __syncthreads();
    if (doRO) {   // 140 threads: (bj = ss, o = oo)
        float m = -INFINITY;
        #pragma unroll
        for (int i = 0; i < OD; i++) m = fmaxf(m, accS[ss][i]);
        float se = 0.0f;
        #pragma unroll
        for (int i = 0; i < OD; i++) se += expf(accS[ss][i] - m);
        out[(size_t)(b0 + ss) * OD + oo] = accS[ss][oo] - m - logf(se);
    }
}

extern "C" void kernel_launch(void* const* d_in, const int* in_sizes, int n_in,
                              void* d_out, int out_size)
{
    const float* x      = (const float*)d_in[0];
    const float* W1     = (const float*)d_in[1];
    const float* b1     = (const float*)d_in[2];
    const float* tau_m1 = (const float*)d_in[3];
    const float* tau_n1 = (const float*)d_in[4];
    const float* W2     = (const float*)d_in[5];
    const float* b2     = (const float*)d_in[6];
    const float* tau_m2 = (const float*)d_in[7];
    float* out = (float*)d_out;

    cudaFuncSetAttribute(snn_r7_kernel,
                         cudaFuncAttributeMaxDynamicSharedMemorySize, SMEM_TOTAL);

    const int B = in_sizes[0] / (3 * TT * 40);   // 512
    snn_r7_kernel<<<B / BPC, NTHR, SMEM_TOTAL>>>(x, W1, b1, tau_m1, tau_n1,
                                                 W2, b2, tau_m2, out);
}